// round 5
// baseline (speedup 1.0000x reference)
#include <cuda_runtime.h>
#include <cstddef>
#include <cstdint>

#define EPS 1e-8f

static constexpr int B    = 1024;
static constexpr int K    = 512;
static constexpr int E    = 64;
static constexpr int D    = 769;
static constexpr int TOPK = 64;

__device__ float g_aw[B * E];      // normalized anchor weights a
__device__ float g_la[B * E];      // log(a + EPS) via XLA-CPU log
__device__ float g_scores[B * K];
__device__ int   g_idx[B * TOPK];

// ---------------------------------------------------------------------------
// Bit-exact replica of XLA-CPU's GenerateVF32Log (port of Eigen plog /
// Cephes logf): NO fused multiply-adds, exact operation order/association.
// All ops via explicit-rounding intrinsics so ptxas cannot contract to FFMA.
// ---------------------------------------------------------------------------
__device__ __forceinline__ float xla_logf(float xin) {
    // x = max(x, min_norm_pos)  (inputs here are always >= ~1e-8, keep anyway)
    float x = fmaxf(xin, __uint_as_float(0x00800000u));
    uint32_t bits = __float_as_uint(x);
    int emm0 = (int)(bits >> 23) - 126;
    float e = (float)emm0;
    // mantissa in [0.5, 1)
    float m = __uint_as_float((bits & 0x807fffffu) | 0x3f000000u);
    // mask = m < sqrt(0.5)
    bool mask = m < __uint_as_float(0x3f3504f3u);   // 0.70710677f
    float tmp = mask ? m : 0.0f;
    float xx = __fadd_rn(__fsub_rn(m, 1.0f), tmp);
    e = __fsub_rn(e, mask ? 1.0f : 0.0f);

    float z = __fmul_rn(xx, xx);
    float y = 7.0376836292e-2f;
    y = __fadd_rn(__fmul_rn(y, xx), -1.1514610310e-1f);
    y = __fadd_rn(__fmul_rn(y, xx),  1.1676998740e-1f);
    y = __fadd_rn(__fmul_rn(y, xx), -1.2420140846e-1f);
    y = __fadd_rn(__fmul_rn(y, xx),  1.4249322787e-1f);
    y = __fadd_rn(__fmul_rn(y, xx), -1.6668057665e-1f);
    y = __fadd_rn(__fmul_rn(y, xx),  2.0000714765e-1f);
    y = __fadd_rn(__fmul_rn(y, xx), -2.4999993993e-1f);
    y = __fadd_rn(__fmul_rn(y, xx),  3.3333331174e-1f);
    y = __fmul_rn(y, xx);
    y = __fmul_rn(y, z);
    y = __fadd_rn(y, __fmul_rn(e, -2.12194440e-4f));
    y = __fsub_rn(y, __fmul_rn(z, 0.5f));
    float r = __fadd_rn(xx, y);
    r = __fadd_rn(r, __fmul_rn(e, 0.693359375f));
    return r;
}

// XLA-CPU vectorized reduce: 4 lane accumulators + shuffle-halving horizontal
#define NEON_HORIZ(a0, a1, a2, a3) __fadd_rn(__fadd_rn(a0, a2), __fadd_rn(a1, a3))

// ---------------------------------------------------------------------------
// K1: anchor rows. One thread per b, XLA-CPU op order.
// ---------------------------------------------------------------------------
__global__ __launch_bounds__(256) void k_anchor(const float* __restrict__ anchor) {
    int b = blockIdx.x * blockDim.x + threadIdx.x;
    if (b >= B) return;
    const float4* row = (const float4*)(anchor + b * E);
    float4 vv[16];
    float a0 = 0.f, a1 = 0.f, a2 = 0.f, a3 = 0.f;
    #pragma unroll
    for (int c = 0; c < 16; c++) {
        vv[c] = __ldg(row + c);
        a0 = __fadd_rn(a0, __fadd_rn(vv[c].x, EPS));
        a1 = __fadd_rn(a1, __fadd_rn(vv[c].y, EPS));
        a2 = __fadd_rn(a2, __fadd_rn(vv[c].z, EPS));
        a3 = __fadd_rn(a3, __fadd_rn(vv[c].w, EPS));
    }
    float S = NEON_HORIZ(a0, a1, a2, a3);
    const float* vf = (const float*)vv;
    #pragma unroll
    for (int e = 0; e < E; e++) {
        float a = __fdiv_rn(__fadd_rn(vf[e], EPS), S);
        g_aw[b * E + e] = a;
        g_la[b * E + e] = xla_logf(__fadd_rn(a, EPS));
    }
}

// ---------------------------------------------------------------------------
// K2: confusion scores. One thread per (b,k); 128 candidates of one b / CTA.
//   ne = n + eps; S = rowsum(ne)           (4-acc + halving horiz)
//   nn = ne / S                            (div.rn)
//   t  = a * (la - log(nn + eps))          (XLA-CPU log, exact rn ops)
//   kl = rowsum(t); score = -kl
// ---------------------------------------------------------------------------
__global__ __launch_bounds__(128) void k_scores(const float* __restrict__ neg) {
    __shared__ float s_a[E], s_la[E];
    int b = blockIdx.x >> 2;
    int k = ((blockIdx.x & 3) << 7) + threadIdx.x;
    if (threadIdx.x < E) {
        s_a[threadIdx.x]  = g_aw[b * E + threadIdx.x];
        s_la[threadIdx.x] = g_la[b * E + threadIdx.x];
    }
    __syncthreads();

    const float4* row = (const float4*)(neg + ((size_t)b * K + k) * E);
    float4 vv[16];
    float a0 = 0.f, a1 = 0.f, a2 = 0.f, a3 = 0.f;
    #pragma unroll
    for (int c = 0; c < 16; c++) {
        vv[c] = __ldg(row + c);
        a0 = __fadd_rn(a0, __fadd_rn(vv[c].x, EPS));
        a1 = __fadd_rn(a1, __fadd_rn(vv[c].y, EPS));
        a2 = __fadd_rn(a2, __fadd_rn(vv[c].z, EPS));
        a3 = __fadd_rn(a3, __fadd_rn(vv[c].w, EPS));
    }
    float S = NEON_HORIZ(a0, a1, a2, a3);

    const float* vf = (const float*)vv;
    float k0 = 0.f, k1 = 0.f, k2 = 0.f, k3 = 0.f;
    #pragma unroll
    for (int c = 0; c < 16; c++) {
        #pragma unroll
        for (int j = 0; j < 4; j++) {
            int e = 4 * c + j;
            float nn = __fdiv_rn(__fadd_rn(vf[e], EPS), S);
            float ln = xla_logf(__fadd_rn(nn, EPS));
            float t  = __fmul_rn(s_a[e], __fsub_rn(s_la[e], ln));
            if (j == 0) k0 = __fadd_rn(k0, t);
            if (j == 1) k1 = __fadd_rn(k1, t);
            if (j == 2) k2 = __fadd_rn(k2, t);
            if (j == 3) k3 = __fadd_rn(k3, t);
        }
    }
    g_scores[b * K + k] = -NEON_HORIZ(k0, k1, k2, k3);
}

// ---------------------------------------------------------------------------
// K3: per-row top-64 via bitonic sort of 512 (desc, ties -> lower index).
// ---------------------------------------------------------------------------
__global__ __launch_bounds__(512) void k_topk(float* __restrict__ out_scores) {
    __shared__ float ss[K];
    __shared__ int   si[K];
    int b = blockIdx.x, tid = threadIdx.x;
    ss[tid] = g_scores[b * K + tid];
    si[tid] = tid;
    for (int sz = 2; sz <= K; sz <<= 1) {
        for (int j = sz >> 1; j > 0; j >>= 1) {
            __syncthreads();
            int ixj = tid ^ j;
            if (ixj > tid) {
                bool desc = ((tid & sz) == 0);
                float s1 = ss[tid], s2 = ss[ixj];
                int   i1 = si[tid], i2 = si[ixj];
                bool g = (s1 > s2) || (s1 == s2 && i1 < i2);
                if (g != desc) {
                    ss[tid] = s2; ss[ixj] = s1;
                    si[tid] = i2; si[ixj] = i1;
                }
            }
        }
    }
    __syncthreads();
    if (tid < TOPK) {
        out_scores[b * TOPK + tid] = ss[tid];
        g_idx[b * TOPK + tid]      = si[tid];
    }
}

// ---------------------------------------------------------------------------
// K4: gather selected candidate rows (769 f32) — coalesced copy.
// ---------------------------------------------------------------------------
__global__ __launch_bounds__(128) void k_gather(
    const float* __restrict__ cand, float* __restrict__ out_hard)
{
    int blk = blockIdx.x;
    int b = blk >> 6, j = blk & (TOPK - 1);
    int idx = g_idx[b * TOPK + j];
    const float* __restrict__ src = cand + ((size_t)b * K + idx) * D;
    float* __restrict__ dst = out_hard + ((size_t)b * TOPK + j) * D;
    #pragma unroll
    for (int i = threadIdx.x; i < D; i += 128)
        dst[i] = __ldg(src + i);
}

// ---------------------------------------------------------------------------
extern "C" void kernel_launch(void* const* d_in, const int* in_sizes, int n_in,
                              void* d_out, int out_size) {
    const float* anchor = (const float*)d_in[0];
    const float* neg    = (const float*)d_in[1];
    const float* cand   = (const float*)d_in[2];
    float* out        = (float*)d_out;
    float* out_hard   = out;
    float* out_scores = out + (size_t)B * TOPK * D;

    k_anchor<<<4, 256>>>(anchor);
    k_scores<<<B * 4, 128>>>(neg);
    k_topk<<<B, 512>>>(out_scores);
    k_gather<<<B * TOPK, 128>>>(cand, out_hard);
}